// round 1
// baseline (speedup 1.0000x reference)
#include <cuda_runtime.h>
#include <math.h>

// Problem constants (fixed shapes)
#define BATCH 2
#define SEQ   2048
#define DMODEL 512
#define NHEADS 8
#define HDIM  64
#define WIN   32
#define HALFW 16

#define MROWS (BATCH * SEQ)   // 4096

// Scratch buffers (device globals; no allocation allowed)
__device__ float g_Q[MROWS * DMODEL];
__device__ float g_K[MROWS * DMODEL];
__device__ float g_V[MROWS * DMODEL];
__device__ float g_AO[MROWS * DMODEL];

// ---------------------------------------------------------------------------
// GEMM: C[M,N] = A[M,K] @ W[N,K]^T + bias[N]
// BM=BN=64, BK=16, 256 threads, 4x4 per thread.
// ---------------------------------------------------------------------------
#define BM 64
#define BN 64
#define BKK 16

__global__ __launch_bounds__(256) void gemm_bias_kernel(
    const float* __restrict__ A, const float* __restrict__ W,
    const float* __restrict__ bias, float* __restrict__ C,
    int M, int N, int K)
{
    __shared__ float As[BKK][BM];
    __shared__ float Bs[BKK][BN];

    const int tid = threadIdx.x;
    const int block_m = blockIdx.y * BM;
    const int block_n = blockIdx.x * BN;
    const int ty = tid >> 4;        // 0..15
    const int tx = tid & 15;        // 0..15

    const int lr = tid >> 2;        // 0..63 (row within tile for loads)
    const int lc = (tid & 3) << 2;  // 0,4,8,12 (k offset)

    float acc[4][4];
#pragma unroll
    for (int i = 0; i < 4; i++)
#pragma unroll
        for (int j = 0; j < 4; j++) acc[i][j] = 0.f;

    const float* Aptr = A + (size_t)(block_m + lr) * K + lc;
    const float* Wptr = W + (size_t)(block_n + lr) * K + lc;

    for (int k0 = 0; k0 < K; k0 += BKK) {
        float4 av = *reinterpret_cast<const float4*>(Aptr + k0);
        float4 bv = *reinterpret_cast<const float4*>(Wptr + k0);
        As[lc + 0][lr] = av.x; As[lc + 1][lr] = av.y;
        As[lc + 2][lr] = av.z; As[lc + 3][lr] = av.w;
        Bs[lc + 0][lr] = bv.x; Bs[lc + 1][lr] = bv.y;
        Bs[lc + 2][lr] = bv.z; Bs[lc + 3][lr] = bv.w;
        __syncthreads();

#pragma unroll
        for (int kk = 0; kk < BKK; kk++) {
            float4 a4 = *reinterpret_cast<const float4*>(&As[kk][ty << 2]);
            float4 b4 = *reinterpret_cast<const float4*>(&Bs[kk][tx << 2]);
            float ar[4] = {a4.x, a4.y, a4.z, a4.w};
            float br[4] = {b4.x, b4.y, b4.z, b4.w};
#pragma unroll
            for (int i = 0; i < 4; i++)
#pragma unroll
                for (int j = 0; j < 4; j++)
                    acc[i][j] = fmaf(ar[i], br[j], acc[i][j]);
        }
        __syncthreads();
    }

#pragma unroll
    for (int j = 0; j < 4; j++) {
        float bb = bias[block_n + (tx << 2) + j];
#pragma unroll
        for (int i = 0; i < 4; i++) {
            C[(size_t)(block_m + (ty << 2) + i) * N + block_n + (tx << 2) + j] =
                acc[i][j] + bb;
        }
    }
}

// ---------------------------------------------------------------------------
// Local-window attention.
// Grid: (SEQ/32, NHEADS, BATCH). Block: 256 threads = 8 warps.
// Block handles 32 queries of one (b, h). Keys needed: [q0-16, q0+48) = 64.
// Each warp processes 4 queries; lane j handles relative key qi + j.
// ---------------------------------------------------------------------------
__global__ __launch_bounds__(256) void local_attn_kernel(
    const float* __restrict__ Q, const float* __restrict__ K,
    const float* __restrict__ V, float* __restrict__ O)
{
    __shared__ float Qs[32][64];      // broadcast reads only -> no pad needed
    __shared__ float Ksh[64][65];     // pad 65 to avoid bank conflicts
    __shared__ float Vsh[64][65];

    const int b  = blockIdx.z;
    const int h  = blockIdx.y;
    const int q0 = blockIdx.x * 32;
    const int k0 = q0 - HALFW;
    const int tid = threadIdx.x;

    // Load Q tile: 32 rows x 64 cols = 512 float4, 256 threads x 2
#pragma unroll
    for (int i = tid; i < 32 * 16; i += 256) {
        int r = i >> 4;
        int c = (i & 15) << 2;
        float4 v = *reinterpret_cast<const float4*>(
            &Q[((size_t)(b * SEQ + q0 + r) * DMODEL) + h * HDIM + c]);
        Qs[r][c + 0] = v.x; Qs[r][c + 1] = v.y; Qs[r][c + 2] = v.z; Qs[r][c + 3] = v.w;
    }

    // Load K/V tiles: 64 rows x 64 cols = 1024 float4 each
    for (int i = tid; i < 64 * 16; i += 256) {
        int r = i >> 4;
        int c = (i & 15) << 2;
        int g = k0 + r;
        float4 kv = make_float4(0.f, 0.f, 0.f, 0.f);
        float4 vv = make_float4(0.f, 0.f, 0.f, 0.f);
        if (g >= 0 && g < SEQ) {
            size_t base = ((size_t)(b * SEQ + g) * DMODEL) + h * HDIM + c;
            kv = *reinterpret_cast<const float4*>(&K[base]);
            vv = *reinterpret_cast<const float4*>(&V[base]);
        }
        Ksh[r][c + 0] = kv.x; Ksh[r][c + 1] = kv.y; Ksh[r][c + 2] = kv.z; Ksh[r][c + 3] = kv.w;
        Vsh[r][c + 0] = vv.x; Vsh[r][c + 1] = vv.y; Vsh[r][c + 2] = vv.z; Vsh[r][c + 3] = vv.w;
    }
    __syncthreads();

    const int warp = tid >> 5;
    const int lane = tid & 31;
    const float scale = 0.125f;   // 64^-0.5

#pragma unroll
    for (int qq = 0; qq < 4; qq++) {
        const int qi = warp * 4 + qq;        // 0..31
        const int iglob = q0 + qi;
        const int kglob = iglob - HALFW + lane;
        const bool valid = (kglob >= 0) && (kglob < SEQ);

        // score for this lane's key
        const float* kr = &Ksh[qi + lane][0];
        const float* qr = &Qs[qi][0];
        float dot = 0.f;
#pragma unroll
        for (int d = 0; d < HDIM; d++) dot = fmaf(qr[d], kr[d], dot);
        float s = valid ? dot * scale : -INFINITY;

        // warp softmax
        float m = s;
#pragma unroll
        for (int o = 16; o > 0; o >>= 1) m = fmaxf(m, __shfl_xor_sync(0xffffffffu, m, o));
        float p = valid ? __expf(s - m) : 0.f;
        float sum = p;
#pragma unroll
        for (int o = 16; o > 0; o >>= 1) sum += __shfl_xor_sync(0xffffffffu, sum, o);
        float inv = 1.f / sum;

        // out[d] = sum_j p_j * V[qi+j][d], lanes cover d = lane, lane+32
        float acc0 = 0.f, acc1 = 0.f;
#pragma unroll
        for (int j = 0; j < 32; j++) {
            float pj = __shfl_sync(0xffffffffu, p, j);
            acc0 = fmaf(pj, Vsh[qi + j][lane], acc0);
            acc1 = fmaf(pj, Vsh[qi + j][lane + 32], acc1);
        }

        size_t obase = ((size_t)(b * SEQ + iglob) * DMODEL) + h * HDIM;
        O[obase + lane]      = acc0 * inv;
        O[obase + 32 + lane] = acc1 * inv;
    }
}

// ---------------------------------------------------------------------------
// Launch
// ---------------------------------------------------------------------------
extern "C" void kernel_launch(void* const* d_in, const int* in_sizes, int n_in,
                              void* d_out, int out_size)
{
    const float* x  = (const float*)d_in[0];
    const float* Wq = (const float*)d_in[1];
    const float* bq = (const float*)d_in[2];
    const float* Wk = (const float*)d_in[3];
    const float* bk = (const float*)d_in[4];
    const float* Wv = (const float*)d_in[5];
    const float* bv = (const float*)d_in[6];
    const float* Wo = (const float*)d_in[7];
    const float* bo = (const float*)d_in[8];
    float* out = (float*)d_out;

    float *Qp, *Kp, *Vp, *AOp;
    cudaGetSymbolAddress((void**)&Qp,  g_Q);
    cudaGetSymbolAddress((void**)&Kp,  g_K);
    cudaGetSymbolAddress((void**)&Vp,  g_V);
    cudaGetSymbolAddress((void**)&AOp, g_AO);

    dim3 gemm_grid(DMODEL / BN, MROWS / BM);   // (8, 64)
    dim3 gemm_blk(256);

    gemm_bias_kernel<<<gemm_grid, gemm_blk>>>(x, Wq, bq, Qp, MROWS, DMODEL, DMODEL);
    gemm_bias_kernel<<<gemm_grid, gemm_blk>>>(x, Wk, bk, Kp, MROWS, DMODEL, DMODEL);
    gemm_bias_kernel<<<gemm_grid, gemm_blk>>>(x, Wv, bv, Vp, MROWS, DMODEL, DMODEL);

    dim3 attn_grid(SEQ / 32, NHEADS, BATCH);   // (64, 8, 2)
    local_attn_kernel<<<attn_grid, 256>>>(Qp, Kp, Vp, AOp);

    gemm_bias_kernel<<<gemm_grid, gemm_blk>>>(AOp, Wo, bo, out, MROWS, DMODEL, DMODEL);
}

// round 3
// speedup vs baseline: 2.8310x; 2.8310x over previous
#include <cuda_runtime.h>
#include <cuda_bf16.h>
#include <math.h>
#include <stdint.h>

// Problem constants (fixed shapes)
#define BATCH 2
#define SEQ   2048
#define DMODEL 512
#define NHEADS 8
#define HDIM  64
#define HALFW 16
#define MROWS (BATCH * SEQ)   // 4096
#define WSZ   (DMODEL * DMODEL)

// ---------------------------------------------------------------------------
// Scratch (device globals; no allocation allowed)
// ---------------------------------------------------------------------------
__device__ float g_Q[MROWS * DMODEL];
__device__ float g_K[MROWS * DMODEL];
__device__ float g_V[MROWS * DMODEL];
__device__ __nv_bfloat16 g_xhi[MROWS * DMODEL];
__device__ __nv_bfloat16 g_xlo[MROWS * DMODEL];
__device__ __nv_bfloat16 g_aohi[MROWS * DMODEL];
__device__ __nv_bfloat16 g_aolo[MROWS * DMODEL];
__device__ __nv_bfloat16 g_Whi[4 * WSZ];
__device__ __nv_bfloat16 g_Wlo[4 * WSZ];

// ---------------------------------------------------------------------------
// PTX helpers (sm_80+ baseline only — NO tcgen05; harness compiles compute_103)
// ---------------------------------------------------------------------------
__device__ __forceinline__ uint32_t smem_to_u32(const void* p) {
    uint32_t a;
    asm("{ .reg .u64 t; cvta.to.shared.u64 t, %1; cvt.u32.u64 %0, t; }" : "=r"(a) : "l"(p));
    return a;
}

__device__ __forceinline__ void cp_async16(uint32_t dst, const void* src) {
    asm volatile("cp.async.cg.shared.global [%0], [%1], 16;" :: "r"(dst), "l"(src));
}
__device__ __forceinline__ void cp_commit() {
    asm volatile("cp.async.commit_group;");
}
template <int N> __device__ __forceinline__ void cp_wait() {
    asm volatile("cp.async.wait_group %0;" :: "n"(N));
}

__device__ __forceinline__ void ldmx4(uint32_t* r, uint32_t addr) {
    asm volatile("ldmatrix.sync.aligned.m8n8.x4.shared.b16 {%0,%1,%2,%3}, [%4];"
                 : "=r"(r[0]), "=r"(r[1]), "=r"(r[2]), "=r"(r[3]) : "r"(addr));
}

__device__ __forceinline__ void mma16816(float* c, const uint32_t* a, const uint32_t* b) {
    asm volatile(
        "mma.sync.aligned.m16n8k16.row.col.f32.bf16.bf16.f32 "
        "{%0,%1,%2,%3}, {%4,%5,%6,%7}, {%8,%9}, {%0,%1,%2,%3};"
        : "+f"(c[0]), "+f"(c[1]), "+f"(c[2]), "+f"(c[3])
        : "r"(a[0]), "r"(a[1]), "r"(a[2]), "r"(a[3]), "r"(b[0]), "r"(b[1]));
}

// ---------------------------------------------------------------------------
// Split fp32 -> bf16 hi + bf16 lo (vectorized x4)
// ---------------------------------------------------------------------------
__device__ __forceinline__ void split4(float4 v, __nv_bfloat162* hi2, __nv_bfloat162* lo2) {
    __nv_bfloat16 hx = __float2bfloat16(v.x), hy = __float2bfloat16(v.y);
    __nv_bfloat16 hz = __float2bfloat16(v.z), hw = __float2bfloat16(v.w);
    hi2[0] = __halves2bfloat162(hx, hy);
    hi2[1] = __halves2bfloat162(hz, hw);
    lo2[0] = __halves2bfloat162(__float2bfloat16(v.x - __bfloat162float(hx)),
                                __float2bfloat16(v.y - __bfloat162float(hy)));
    lo2[1] = __halves2bfloat162(__float2bfloat16(v.z - __bfloat162float(hz)),
                                __float2bfloat16(v.w - __bfloat162float(hw)));
}

__global__ void split_x_kernel(const float4* __restrict__ src,
                               __nv_bfloat162* __restrict__ hi,
                               __nv_bfloat162* __restrict__ lo, int n4)
{
    int i = blockIdx.x * blockDim.x + threadIdx.x;
    if (i < n4) {
        __nv_bfloat162 h[2], l[2];
        split4(src[i], h, l);
        hi[2 * i] = h[0]; hi[2 * i + 1] = h[1];
        lo[2 * i] = l[0]; lo[2 * i + 1] = l[1];
    }
}

__global__ void split_w_kernel(const float4* __restrict__ w0, const float4* __restrict__ w1,
                               const float4* __restrict__ w2, const float4* __restrict__ w3,
                               __nv_bfloat162* __restrict__ hi,
                               __nv_bfloat162* __restrict__ lo)
{
    const int per = WSZ / 4;
    int i = blockIdx.x * blockDim.x + threadIdx.x;
    if (i < 4 * per) {
        int sel = i / per, j = i - sel * per;
        const float4* s = (sel == 0) ? w0 : (sel == 1) ? w1 : (sel == 2) ? w2 : w3;
        __nv_bfloat162 h[2], l[2];
        split4(s[j], h, l);
        hi[2 * i] = h[0]; hi[2 * i + 1] = h[1];
        lo[2 * i] = l[0]; lo[2 * i + 1] = l[1];
    }
}

// ---------------------------------------------------------------------------
// bf16x3 tensor-core GEMM: C[M,N] = (Ahi+Alo) @ (Whi+Wlo)^T + bias (lo*lo dropped)
// A: [M,512] row-major bf16 (hi/lo). W: [N,512] row-major bf16 (hi/lo).
// CTA tile 128x128, BK=32, 256 threads = 8 warps (4m x 2n), warptile 32x64.
// Double-buffered cp.async. grid.z picks (W, bias, C) set for fused QKV.
// ---------------------------------------------------------------------------
#define ROWB 80                  // smem row stride bytes (64B data + 16B pad)
#define TILEB (128 * ROWB)       // 10240 per tile
#define STAGEB (4 * TILEB)       // Ahi, Alo, Bhi, Blo
#define GEMM_SMEM (2 * STAGEB)   // 81920

__global__ __launch_bounds__(256) void mma_gemm_kernel(
    const __nv_bfloat16* __restrict__ Ahi, const __nv_bfloat16* __restrict__ Alo,
    const __nv_bfloat16* __restrict__ Whi_base, const __nv_bfloat16* __restrict__ Wlo_base,
    const float* __restrict__ b0, float* __restrict__ C0,
    const float* __restrict__ b1, float* __restrict__ C1,
    const float* __restrict__ b2, float* __restrict__ C2)
{
    extern __shared__ __align__(128) char smem[];
    const uint32_t smem_u = smem_to_u32(smem);

    const int z = blockIdx.z;
    const __nv_bfloat16* Whi = Whi_base + (size_t)z * WSZ;
    const __nv_bfloat16* Wlo = Wlo_base + (size_t)z * WSZ;
    const float* bias = (z == 0) ? b0 : (z == 1) ? b1 : b2;
    float* C          = (z == 0) ? C0 : (z == 1) ? C1 : C2;

    const int tid = threadIdx.x;
    const int lane = tid & 31;
    const int warp = tid >> 5;
    const int wm = warp & 3;          // 0..3  (m offset 32*wm)
    const int wn = warp >> 2;         // 0..1  (n offset 64*wn)
    const int bm = blockIdx.y * 128;
    const int bn = blockIdx.x * 128;

    // ---- loader addressing (per thread: 2 rows x 1 col16 per tile) ----
    const int lrow0 = tid >> 2;              // 0..63
    const int lc16  = tid & 3;               // 16B column 0..3
    const uint32_t so0 = lrow0 * ROWB + lc16 * 16;
    const uint32_t so1 = so0 + 64 * ROWB;
    const char* pAhi = (const char*)Ahi + ((size_t)(bm + lrow0) * DMODEL + lc16 * 8) * 2;
    const char* pAlo = (const char*)Alo + ((size_t)(bm + lrow0) * DMODEL + lc16 * 8) * 2;
    const char* pBhi = (const char*)Whi + ((size_t)(bn + lrow0) * DMODEL + lc16 * 8) * 2;
    const char* pBlo = (const char*)Wlo + ((size_t)(bn + lrow0) * DMODEL + lc16 * 8) * 2;
    const size_t rowadd = (size_t)64 * DMODEL * 2;   // +64 rows

#define PREFETCH(kc, s) do {                                                   \
    uint32_t base = smem_u + (s) * STAGEB;                                     \
    int kb = (kc) * 64;  /* 32 bf16 = 64 bytes */                              \
    cp_async16(base + 0 * TILEB + so0, pAhi + kb);                             \
    cp_async16(base + 0 * TILEB + so1, pAhi + rowadd + kb);                    \
    cp_async16(base + 1 * TILEB + so0, pAlo + kb);                             \
    cp_async16(base + 1 * TILEB + so1, pAlo + rowadd + kb);                    \
    cp_async16(base + 2 * TILEB + so0, pBhi + kb);                             \
    cp_async16(base + 2 * TILEB + so1, pBhi + rowadd + kb);                    \
    cp_async16(base + 3 * TILEB + so0, pBlo + kb);                             \
    cp_async16(base + 3 * TILEB + so1, pBlo + rowadd + kb);                    \
    cp_commit();                                                               \
} while (0)

    // ---- ldmatrix lane addressing ----
    const uint32_t a_row = lane & 15;
    const uint32_t a_koff = (lane >> 4) * 16;
    const uint32_t b_row = (lane & 7) + (lane >> 4) * 8;
    const uint32_t b_koff = ((lane >> 3) & 1) * 16;

    float acc[2][8][4];
#pragma unroll
    for (int mt = 0; mt < 2; mt++)
#pragma unroll
        for (int nt = 0; nt < 8; nt++)
#pragma unroll
            for (int r = 0; r < 4; r++) acc[mt][nt][r] = 0.f;

    const int NKC = DMODEL / 32;  // 16
    PREFETCH(0, 0);

    for (int kc = 0; kc < NKC; kc++) {
        const int s = kc & 1;
        cp_wait<0>();
        __syncthreads();
        if (kc + 1 < NKC) PREFETCH(kc + 1, s ^ 1);

        const uint32_t stage = smem_u + s * STAGEB;
#pragma unroll
        for (int ks = 0; ks < 2; ks++) {
            const uint32_t kb = ks * 32;  // 16 bf16 = 32 bytes
            uint32_t ahi[2][4], alo[2][4], bhi[4][4], blo[4][4];
#pragma unroll
            for (int mt = 0; mt < 2; mt++) {
                uint32_t ra = (wm * 32 + mt * 16 + a_row) * ROWB + kb + a_koff;
                ldmx4(ahi[mt], stage + 0 * TILEB + ra);
                ldmx4(alo[mt], stage + 1 * TILEB + ra);
            }
#pragma unroll
            for (int g = 0; g < 4; g++) {
                uint32_t rb = (wn * 64 + g * 16 + b_row) * ROWB + kb + b_koff;
                ldmx4(bhi[g], stage + 2 * TILEB + rb);
                ldmx4(blo[g], stage + 3 * TILEB + rb);
            }
#pragma unroll
            for (int mt = 0; mt < 2; mt++)
#pragma unroll
                for (int nt = 0; nt < 8; nt++) {
                    const int g = nt >> 1, h = (nt & 1) * 2;
                    uint32_t bh[2] = {bhi[g][h], bhi[g][h + 1]};
                    uint32_t bl[2] = {blo[g][h], blo[g][h + 1]};
                    mma16816(acc[mt][nt], ahi[mt], bh);
                    mma16816(acc[mt][nt], ahi[mt], bl);
                    mma16816(acc[mt][nt], alo[mt], bh);
                }
        }
        __syncthreads();
    }

    // ---- epilogue: bias add + fp32 store ----
#pragma unroll
    for (int mt = 0; mt < 2; mt++) {
        const int row = bm + wm * 32 + mt * 16 + (lane >> 2);
#pragma unroll
        for (int nt = 0; nt < 8; nt++) {
            const int col = bn + wn * 64 + nt * 8 + (lane & 3) * 2;
            float2 bv = *(const float2*)(bias + col);
            float2 o0 = make_float2(acc[mt][nt][0] + bv.x, acc[mt][nt][1] + bv.y);
            float2 o1 = make_float2(acc[mt][nt][2] + bv.x, acc[mt][nt][3] + bv.y);
            *(float2*)(C + (size_t)row * DMODEL + col) = o0;
            *(float2*)(C + (size_t)(row + 8) * DMODEL + col) = o1;
        }
    }
#undef PREFETCH
}

// ---------------------------------------------------------------------------
// Local-window attention. Outputs bf16 hi/lo split for the O-projection.
// Grid: (SEQ/32, NHEADS, BATCH). Block: 256 = 8 warps, 4 queries per warp.
// ---------------------------------------------------------------------------
__global__ __launch_bounds__(256) void local_attn_kernel(
    const float* __restrict__ Q, const float* __restrict__ K,
    const float* __restrict__ V,
    __nv_bfloat16* __restrict__ Ohi, __nv_bfloat16* __restrict__ Olo)
{
    __shared__ float Qs[32][64];
    __shared__ float Ksh[64][65];
    __shared__ float Vsh[64][65];

    const int b  = blockIdx.z;
    const int h  = blockIdx.y;
    const int q0 = blockIdx.x * 32;
    const int k0 = q0 - HALFW;
    const int tid = threadIdx.x;

#pragma unroll
    for (int i = tid; i < 32 * 16; i += 256) {
        int r = i >> 4;
        int c = (i & 15) << 2;
        float4 v = *reinterpret_cast<const float4*>(
            &Q[((size_t)(b * SEQ + q0 + r) * DMODEL) + h * HDIM + c]);
        Qs[r][c + 0] = v.x; Qs[r][c + 1] = v.y; Qs[r][c + 2] = v.z; Qs[r][c + 3] = v.w;
    }
    for (int i = tid; i < 64 * 16; i += 256) {
        int r = i >> 4;
        int c = (i & 15) << 2;
        int g = k0 + r;
        float4 kv = make_float4(0.f, 0.f, 0.f, 0.f);
        float4 vv = make_float4(0.f, 0.f, 0.f, 0.f);
        if (g >= 0 && g < SEQ) {
            size_t base = ((size_t)(b * SEQ + g) * DMODEL) + h * HDIM + c;
            kv = *reinterpret_cast<const float4*>(&K[base]);
            vv = *reinterpret_cast<const float4*>(&V[base]);
        }
        Ksh[r][c + 0] = kv.x; Ksh[r][c + 1] = kv.y; Ksh[r][c + 2] = kv.z; Ksh[r][c + 3] = kv.w;
        Vsh[r][c + 0] = vv.x; Vsh[r][c + 1] = vv.y; Vsh[r][c + 2] = vv.z; Vsh[r][c + 3] = vv.w;
    }
    __syncthreads();

    const int warp = tid >> 5;
    const int lane = tid & 31;
    const float scale = 0.125f;

#pragma unroll
    for (int qq = 0; qq < 4; qq++) {
        const int qi = warp * 4 + qq;
        const int iglob = q0 + qi;
        const int kglob = iglob - HALFW + lane;
        const bool valid = (kglob >= 0) && (kglob < SEQ);

        const float* kr = &Ksh[qi + lane][0];
        const float* qr = &Qs[qi][0];
        float dot = 0.f;
#pragma unroll
        for (int d = 0; d < HDIM; d++) dot = fmaf(qr[d], kr[d], dot);
        float s = valid ? dot * scale : -INFINITY;

        float m = s;
#pragma unroll
        for (int o = 16; o > 0; o >>= 1) m = fmaxf(m, __shfl_xor_sync(0xffffffffu, m, o));
        float p = valid ? __expf(s - m) : 0.f;
        float sum = p;
#pragma unroll
        for (int o = 16; o > 0; o >>= 1) sum += __shfl_xor_sync(0xffffffffu, sum, o);
        float inv = 1.f / sum;

        float acc0 = 0.f, acc1 = 0.f;
#pragma unroll
        for (int j = 0; j < 32; j++) {
            float pj = __shfl_sync(0xffffffffu, p, j);
            acc0 = fmaf(pj, Vsh[qi + j][lane], acc0);
            acc1 = fmaf(pj, Vsh[qi + j][lane + 32], acc1);
        }

        float v0 = acc0 * inv;
        float v1 = acc1 * inv;
        size_t obase = ((size_t)(b * SEQ + iglob) * DMODEL) + h * HDIM;
        __nv_bfloat16 h0 = __float2bfloat16(v0);
        __nv_bfloat16 h1 = __float2bfloat16(v1);
        Ohi[obase + lane]      = h0;
        Ohi[obase + 32 + lane] = h1;
        Olo[obase + lane]      = __float2bfloat16(v0 - __bfloat162float(h0));
        Olo[obase + 32 + lane] = __float2bfloat16(v1 - __bfloat162float(h1));
    }
}

// ---------------------------------------------------------------------------
// Launch
// ---------------------------------------------------------------------------
extern "C" void kernel_launch(void* const* d_in, const int* in_sizes, int n_in,
                              void* d_out, int out_size)
{
    const float* x  = (const float*)d_in[0];
    const float* Wq = (const float*)d_in[1];
    const float* bq = (const float*)d_in[2];
    const float* Wk = (const float*)d_in[3];
    const float* bk = (const float*)d_in[4];
    const float* Wv = (const float*)d_in[5];
    const float* bv = (const float*)d_in[6];
    const float* Wo = (const float*)d_in[7];
    const float* bo = (const float*)d_in[8];
    float* out = (float*)d_out;

    float *Qp, *Kp, *Vp;
    __nv_bfloat16 *xhi, *xlo, *aohi, *aolo, *Whi, *Wlo;
    cudaGetSymbolAddress((void**)&Qp,  g_Q);
    cudaGetSymbolAddress((void**)&Kp,  g_K);
    cudaGetSymbolAddress((void**)&Vp,  g_V);
    cudaGetSymbolAddress((void**)&xhi, g_xhi);
    cudaGetSymbolAddress((void**)&xlo, g_xlo);
    cudaGetSymbolAddress((void**)&aohi, g_aohi);
    cudaGetSymbolAddress((void**)&aolo, g_aolo);
    cudaGetSymbolAddress((void**)&Whi, g_Whi);
    cudaGetSymbolAddress((void**)&Wlo, g_Wlo);

    cudaFuncSetAttribute(mma_gemm_kernel, cudaFuncAttributeMaxDynamicSharedMemorySize,
                         GEMM_SMEM);

    // Splits: x and the 4 weights (order in g_Whi: Wq, Wk, Wv, Wo)
    const int NX4 = (MROWS * DMODEL) / 4;
    split_x_kernel<<<(NX4 + 255) / 256, 256>>>(
        (const float4*)x, (__nv_bfloat162*)xhi, (__nv_bfloat162*)xlo, NX4);
    const int NW4 = WSZ;  // 4 * WSZ / 4
    split_w_kernel<<<(NW4 + 255) / 256, 256>>>(
        (const float4*)Wq, (const float4*)Wk, (const float4*)Wv, (const float4*)Wo,
        (__nv_bfloat162*)Whi, (__nv_bfloat162*)Wlo);

    // Fused Q/K/V projection
    dim3 qkv_grid(DMODEL / 128, MROWS / 128, 3);   // (4, 32, 3)
    mma_gemm_kernel<<<qkv_grid, 256, GEMM_SMEM>>>(
        xhi, xlo, Whi, Wlo,
        bq, Qp, bk, Kp, bv, Vp);

    // Local attention -> bf16 hi/lo
    dim3 attn_grid(SEQ / 32, NHEADS, BATCH);
    local_attn_kernel<<<attn_grid, 256>>>(Qp, Kp, Vp, aohi, aolo);

    // Output projection (weight set 3 = Wo)
    dim3 o_grid(DMODEL / 128, MROWS / 128, 1);
    mma_gemm_kernel<<<o_grid, 256, GEMM_SMEM>>>(
        aohi, aolo, Whi + 3 * WSZ, Wlo + 3 * WSZ,
        bo, out, bo, out, bo, out);
}